// round 16
// baseline (speedup 1.0000x reference)
#include <cuda_runtime.h>
#include <cstdint>
#include <math.h>

// ---------------- problem constants ----------------
#define NROWS 8192
#define DKK   64
#define GMODES 16

// ---------------- static device scratch (no runtime alloc) ----------------
__device__ __align__(16) float g_colpart[2][64][64];
__device__ float g_sqpart[2][64];
__device__ float g_stats[2][65];
__device__ __align__(16) float g_kg[GMODES][64];
__device__ __align__(16) float g_Wf[GMODES * 64][64];   // Wf[g*64+j][i] = tf32(W_s[g][i][j])
__device__ __align__(16) float g_alpha[NROWS][GMODES];
__device__ __align__(16) float g_prop[NROWS][64];       // tf32-rounded propagated[n][i]
__device__ __align__(16) float g_part[8][NROWS][64];    // split-k partials (fp32), k-eighths

// ---------------- helpers ----------------
#define DI static __device__ __forceinline__

DI uint32_t f2tf32(float x) {
    uint32_t r;
    asm("cvt.rna.tf32.f32 %0, %1;" : "=r"(r) : "f"(x));
    return r;
}
DI float round_tf32(float x) { return __uint_as_float(f2tf32(x)); }

DI void mma8(float c[4], uint32_t a0, uint32_t a1, uint32_t a2, uint32_t a3,
             uint32_t b0, uint32_t b1) {
    asm volatile(
        "mma.sync.aligned.m16n8k8.row.col.f32.tf32.tf32.f32 "
        "{%0,%1,%2,%3},{%4,%5,%6,%7},{%8,%9},{%0,%1,%2,%3};\n"
        : "+f"(c[0]), "+f"(c[1]), "+f"(c[2]), "+f"(c[3])
        : "r"(a0), "r"(a1), "r"(a2), "r"(a3), "r"(b0), "r"(b1));
}

DI void cpa16(void* smem, const void* g) {
    uint32_t s = (uint32_t)__cvta_generic_to_shared(smem);
    asm volatile("cp.async.cg.shared.global [%0], [%1], 16;\n" :: "r"(s), "l"(g));
}
DI void cpa_commit() { asm volatile("cp.async.commit_group;\n"); }
template <int NPEND> DI void cpa_wait() { asm volatile("cp.async.wait_group %0;\n" :: "n"(NPEND)); }

DI uint32_t rotl32(uint32_t x, int r) { return (x << r) | (x >> (32 - r)); }

// JAX threefry2x32-20, key (0,42), partitionable: counter (0, m), out = bits1 ^ bits2
DI float gumbel_for(int m) {
    uint32_t x0 = 0u, x1 = (uint32_t)m;
    const uint32_t k0 = 0u, k1 = 42u, k2 = 0u ^ 42u ^ 0x1BD11BDAu;
    const int R0[4] = {13, 15, 26, 6}, R1[4] = {17, 29, 16, 24};
    x0 += k0; x1 += k1;
    #pragma unroll
    for (int i = 0; i < 4; i++) { x0 += x1; x1 = rotl32(x1, R0[i]); x1 ^= x0; }
    x0 += k1; x1 += k2 + 1u;
    #pragma unroll
    for (int i = 0; i < 4; i++) { x0 += x1; x1 = rotl32(x1, R1[i]); x1 ^= x0; }
    x0 += k2; x1 += k0 + 2u;
    #pragma unroll
    for (int i = 0; i < 4; i++) { x0 += x1; x1 = rotl32(x1, R0[i]); x1 ^= x0; }
    x0 += k0; x1 += k1 + 3u;
    #pragma unroll
    for (int i = 0; i < 4; i++) { x0 += x1; x1 = rotl32(x1, R1[i]); x1 ^= x0; }
    x0 += k1; x1 += k2 + 4u;
    #pragma unroll
    for (int i = 0; i < 4; i++) { x0 += x1; x1 = rotl32(x1, R0[i]); x1 ^= x0; }
    x0 += k2; x1 += k0 + 5u;
    uint32_t bits = x0 ^ x1;
    float u = __uint_as_float((bits >> 9) | 0x3f800000u) - 1.0f;
    u = fmaxf(u, 0.0f);
    return -logf(-logf(u + 1e-10f) + 1e-10f);
}

// ---------------- K0: partial stats for P_in / A_in ----------------
__global__ void sagr_stats(const float* __restrict__ Pin, const float* __restrict__ Ain) {
    __shared__ float scs[256], sss[256];
    int b = blockIdx.x, t = threadIdx.x;
    int which = b >> 6, bb = b & 63;
    const float* X = which ? Ain : Pin;
    int c = t & 63, r0 = t >> 6;
    const float* base = X + (size_t)bb * 128 * 64;
    float cs = 0.f, ss = 0.f;
    for (int r = r0; r < 128; r += 4) { float v = base[r * 64 + c]; cs += v; ss += v * v; }
    scs[t] = cs; sss[t] = ss;
    __syncthreads();
    if (t < 64) g_colpart[which][bb][t] = scs[t] + scs[t + 64] + scs[t + 128] + scs[t + 192];
    __syncthreads();
    if (t < 128) sss[t] += sss[t + 128];
    __syncthreads();
    if (t < 64) sss[t] += sss[t + 64];
    __syncthreads();
    if (t < 32) {
        float v = sss[t] + sss[t + 32];
        for (int o = 16; o > 0; o >>= 1) v += __shfl_down_sync(0xffffffffu, v, o);
        if (t == 0) g_sqpart[which][bb] = v;
    }
}

// ---------------- K1: finalize stats ----------------
__global__ void sagr_finalize() {
    int t = threadIdx.x;
    if (t < 128) {
        int which = t >> 6, c = t & 63;
        float s = 0.f;
        for (int bb = 0; bb < 64; bb++) s += g_colpart[which][bb][c];
        g_stats[which][c] = s / 8192.0f;
    } else if (t == 128 || t == 129) {
        int which = t - 128;
        float s = 0.f;
        for (int bb = 0; bb < 64; bb++) s += g_sqpart[which][bb];
        g_stats[which][64] = s / 524288.0f;
    }
}

// ---------------- K2: k_g[g][i] = Ws_flat[g] . Wkw[i] + Wkb[i] ----------------
__global__ void sagr_kg(const float* __restrict__ Ws, const float* __restrict__ Wkw,
                        const float* __restrict__ Wkb) {
    __shared__ float wk_s[4096];
    __shared__ float red[8];
    int i = blockIdx.x, t = threadIdx.x;
    for (int f = t; f < 4096; f += 256) wk_s[f] = Wkw[i * 4096 + f];
    __syncthreads();
    float bias = Wkb[i];
    for (int g = 0; g < GMODES; g++) {
        const float* w = Ws + g * 4096;
        float p = 0.f;
        for (int f = t; f < 4096; f += 256) p += w[f] * wk_s[f];
        for (int o = 16; o > 0; o >>= 1) p += __shfl_down_sync(0xffffffffu, p, o);
        if ((t & 31) == 0) red[t >> 5] = p;
        __syncthreads();
        if (t == 0) {
            float s = 0.f;
            for (int ww = 0; ww < 8; ww++) s += red[ww];
            g_kg[g][i] = s + bias;
        }
        __syncthreads();
    }
}

// ---------------- K3: Wf transpose via smem (1024 threads, coalesced both sides) ----------------
__global__ __launch_bounds__(1024) void sagr_wf(const float* __restrict__ Ws) {
    __shared__ float s[64 * 65];
    int g = blockIdx.x, t = threadIdx.x;
    for (int idx = t; idx < 4096; idx += 1024) {
        int i = idx >> 6, j = idx & 63;
        s[j * 65 + i] = Ws[g * 4096 + idx];
    }
    __syncthreads();
    for (int idx = t; idx < 4096; idx += 1024) {
        int row = idx >> 6, col = idx & 63;
        g_Wf[g * 64 + row][col] = round_tf32(s[row * 65 + col]);
    }
}

// ---------------- K4: fused per-row ops ----------------
__global__ __launch_bounds__(256) void sagr_rowops(
    const float* __restrict__ z, const float* __restrict__ Pref, const float* __restrict__ Aref,
    const float* __restrict__ Wiw, const float* __restrict__ Wib,
    const float* __restrict__ Wgw, const float* __restrict__ Wgb,
    const float* __restrict__ Wsw, const float* __restrict__ Wsb,
    float* __restrict__ out) {
    extern __shared__ float sm[];
    float* z_s  = sm;
    float* wi_s = sm + 4160;
    float* wg_s = sm + 8320;
    float* q_s  = sm + 12480;
    float* kg_s = sm + 16640;
    float* dp_s = sm + 17680;
    float* da_s = sm + 17744;
    int t = threadIdx.x, blk = blockIdx.x, row0 = blk * 64;

    for (int idx = t; idx < 4096; idx += 256) {
        int r = idx >> 6, c = idx & 63;
        z_s[r * 65 + c]  = z[(row0 + r) * 64 + c];
        wi_s[r * 65 + c] = Wiw[idx];
        wg_s[r * 65 + c] = Wgw[idx];
    }
    for (int idx = t; idx < 1024; idx += 256) {
        int g = idx >> 6, c = idx & 63;
        kg_s[g * 65 + c] = g_kg[g][c];
    }
    {
        int r = t >> 2, u = t & 3, n = row0 + r;
        float dotP = 0.f, sqP = 0.f, dotA = 0.f, sqA = 0.f;
        for (int kk = 0; kk < 16; kk++) {
            int k = u * 16 + kk;
            float pv = Pref[n * 64 + k]; dotP += pv * g_stats[0][k]; sqP += pv * pv;
            float av = Aref[n * 64 + k]; dotA += av * g_stats[1][k]; sqA += av * av;
        }
        dotP += __shfl_xor_sync(0xffffffffu, dotP, 1); dotP += __shfl_xor_sync(0xffffffffu, dotP, 2);
        sqP  += __shfl_xor_sync(0xffffffffu, sqP, 1);  sqP  += __shfl_xor_sync(0xffffffffu, sqP, 2);
        dotA += __shfl_xor_sync(0xffffffffu, dotA, 1); dotA += __shfl_xor_sync(0xffffffffu, dotA, 2);
        sqA  += __shfl_xor_sync(0xffffffffu, sqA, 1);  sqA  += __shfl_xor_sync(0xffffffffu, sqA, 2);
        if (u == 0) {
            dp_s[r] = g_stats[0][64] - 2.0f * dotP / 64.0f + sqP / 64.0f;
            da_s[r] = g_stats[1][64] - 2.0f * dotA / 64.0f + sqA / 64.0f;
        }
    }
    __syncthreads();
    {
        int grp = t >> 4, il = t & 15;
        int r0 = grp * 4, i0 = il * 4;
        float aI[4][4] = {}, aG[4][4] = {};
        for (int j = 0; j < 64; j++) {
            float zz[4], wi4[4], wg4[4];
            #pragma unroll
            for (int rr = 0; rr < 4; rr++) zz[rr] = z_s[(r0 + rr) * 65 + j];
            #pragma unroll
            for (int ii = 0; ii < 4; ii++) { wi4[ii] = wi_s[(i0 + ii) * 65 + j]; wg4[ii] = wg_s[(i0 + ii) * 65 + j]; }
            #pragma unroll
            for (int rr = 0; rr < 4; rr++)
                #pragma unroll
                for (int ii = 0; ii < 4; ii++) {
                    aI[rr][ii] += zz[rr] * wi4[ii];
                    aG[rr][ii] += zz[rr] * wg4[ii];
                }
        }
        #pragma unroll
        for (int ii = 0; ii < 4; ii++) {
            int i = i0 + ii;
            float bi = Wib[i], bg = Wgb[i], bs = Wsb[i];
            float w0 = Wsw[i * 2 + 0], w1 = Wsw[i * 2 + 1];
            #pragma unroll
            for (int rr = 0; rr < 4; rr++) {
                int r = r0 + rr;
                float gate = 1.0f / (1.0f + expf(-(aG[rr][ii] + bg)));
                float sys = da_s[r] * w0 + dp_s[r] * w1 + bs;
                q_s[r * 65 + i] = aI[rr][ii] + bi + gate * sys;
            }
        }
    }
    __syncthreads();
    {
        int r = t >> 2, u = t & 3, n = row0 + r;
        float acc[4] = {0.f, 0.f, 0.f, 0.f};
        for (int i = 0; i < 64; i++) {
            float qv = q_s[r * 65 + i];
            #pragma unroll
            for (int gg = 0; gg < 4; gg++) acc[gg] += qv * kg_s[(u * 4 + gg) * 65 + i];
        }
        float e[4], mx = -1e30f;
        #pragma unroll
        for (int gg = 0; gg < 4; gg++) {
            int g = u * 4 + gg;
            float s = acc[gg] * 0.125f;
            out[NROWS * 64 + n * 16 + g] = s;
            e[gg] = s + gumbel_for(n * 16 + g);
            mx = fmaxf(mx, e[gg]);
        }
        mx = fmaxf(mx, __shfl_xor_sync(0xffffffffu, mx, 1));
        mx = fmaxf(mx, __shfl_xor_sync(0xffffffffu, mx, 2));
        float sum = 0.f;
        #pragma unroll
        for (int gg = 0; gg < 4; gg++) { e[gg] = expf(e[gg] - mx); sum += e[gg]; }
        sum += __shfl_xor_sync(0xffffffffu, sum, 1);
        sum += __shfl_xor_sync(0xffffffffu, sum, 2);
        float inv = 1.0f / sum;
        #pragma unroll
        for (int gg = 0; gg < 4; gg++) g_alpha[n][u * 4 + gg] = e[gg] * inv;
    }
}

// ---------------- K5: propagated = (alpha (x) z) @ Wf, tf32 mma; 3-buffer overlap ----------------
__global__ __launch_bounds__(128) void sagr_prop(const float* __restrict__ z) {
    extern __shared__ float sm[];
    float* z_s  = sm;               // 64 x 72
    float* al_s = sm + 4608;        // 64 x 17
    float* wf_s = sm + 5696;        // 3 buffers of 64 x 72
    int t = threadIdx.x, w = t >> 5, lane = t & 31;
    int gid = lane >> 2, tig = lane & 3;
    int row0 = blockIdx.x * 64;

    for (int idx = t; idx < 4096; idx += 128) {
        int r = idx >> 6, c = idx & 63;
        z_s[r * 72 + c] = z[(row0 + r) * 64 + c];
    }
    for (int idx = t; idx < 1024; idx += 128) {
        int r = idx >> 4, g = idx & 15;
        al_s[r * 17 + g] = g_alpha[row0 + r][g];
    }
    auto issue = [&](int g, int buf) {
        #pragma unroll
        for (int it = 0; it < 8; it++) {
            int chunk = it * 128 + t, row = chunk >> 4, cc = chunk & 15;
            cpa16(wf_s + buf * 4608 + row * 72 + cc * 4, &g_Wf[g * 64 + row][cc * 4]);
        }
        cpa_commit();
    };
    issue(0, 0);

    float c[8][4] = {};
    int r0g = w * 16 + gid;
    for (int g = 0; g < GMODES; g++) {
        if (g + 1 < GMODES) issue(g + 1, (g + 1) % 3);
        if (g < GMODES - 1) cpa_wait<1>(); else cpa_wait<0>();
        __syncthreads();
        float* wb = wf_s + (g % 3) * 4608;
        float a_lo = al_s[r0g * 17 + g];
        float a_hi = al_s[(r0g + 8) * 17 + g];
        #pragma unroll
        for (int ks = 0; ks < 8; ks++) {
            int kc = ks * 8 + tig;
            uint32_t a0 = f2tf32(a_lo * z_s[r0g * 72 + kc]);
            uint32_t a1 = f2tf32(a_hi * z_s[(r0g + 8) * 72 + kc]);
            uint32_t a2 = f2tf32(a_lo * z_s[r0g * 72 + kc + 4]);
            uint32_t a3 = f2tf32(a_hi * z_s[(r0g + 8) * 72 + kc + 4]);
            #pragma unroll
            for (int nt = 0; nt < 8; nt++) {
                uint32_t b0 = __float_as_uint(wb[kc * 72 + nt * 8 + gid]);
                uint32_t b1 = __float_as_uint(wb[(kc + 4) * 72 + nt * 8 + gid]);
                mma8(c[nt], a0, a1, a2, a3, b0, b1);
            }
        }
        __syncthreads();
    }
    #pragma unroll
    for (int nt = 0; nt < 8; nt++)
        #pragma unroll
        for (int q = 0; q < 4; q++) {
            int row = r0g + ((q & 2) ? 8 : 0);
            int col = nt * 8 + tig * 2 + (q & 1);
            g_prop[row0 + row][col] = round_tf32(c[nt][q]);
        }
}

// ---------------- K6: persistent split-k hgemm: M=64 tiles x k-eighths ----------------
// grid = 148 CTAs x 128 threads. 1024 units = 128 m64-tiles x 8 k-eighths (16 ktiles).
// Inner loop is byte-identical to the proven R6 kernel; only the k-range is 16
// tiles and the epilogue writes fp32 partials to g_part[k8]. Max CTA load =
// 7 units = 112 ktiles vs 128 today -> ~12.5% less tensor work on the critical path.
__global__ __launch_bounds__(128) void sagr_hgemm6(const float* __restrict__ R) {
    extern __shared__ float sm[];
    int t = threadIdx.x, w = t >> 5, lane = t & 31;
    int gid = lane >> 2, tig = lane & 3;
    int wm = w >> 1, wk = w & 1;
    const float* Pbase = &g_prop[0][0];

    for (int u = blockIdx.x; u < 1024; u += 148) {
        int mt = u >> 3, k8 = u & 7;
        const float* Rbase = R + (size_t)(mt * 64) * 8192;
        int kt0 = k8 * 16;

        auto issue = [&](int ktl, int s) {
            float* As = sm + s * 9216;
            float* Bs = As + 4608;
            const float* ra = Rbase + (kt0 + ktl) * 64;
            #pragma unroll
            for (int it = 0; it < 8; it++) {
                int chunk = it * 128 + t, row = chunk >> 4, cc = chunk & 15;
                cpa16(As + row * 72 + cc * 4, ra + (size_t)row * 8192 + cc * 4);
            }
            const float* pb = Pbase + (size_t)(kt0 + ktl) * 64 * 64;
            #pragma unroll
            for (int it = 0; it < 8; it++) {
                int chunk = it * 128 + t, row = chunk >> 4, cc = chunk & 15;
                cpa16(Bs + row * 72 + cc * 4, pb + row * 64 + cc * 4);
            }
        };

        issue(0, 0); cpa_commit();
        issue(1, 1); cpa_commit();
        issue(2, 2); cpa_commit();

        float c[2][8][4] = {};
        for (int ktl = 0; ktl < 16; ktl++) {
            cpa_wait<2>();
            __syncthreads();
            if (ktl + 3 < 16) issue(ktl + 3, (ktl + 3) & 3);
            cpa_commit();
            float* As = sm + (ktl & 3) * 9216;
            float* Bs = As + 4608;
            #pragma unroll
            for (int ks = 0; ks < 4; ks++) {
                int kc = wk * 32 + ks * 8 + tig;
                uint32_t af[2][4];
                #pragma unroll
                for (int mt2 = 0; mt2 < 2; mt2++) {
                    int rb = wm * 32 + mt2 * 16;
                    af[mt2][0] = f2tf32(As[(rb + gid) * 72 + kc]);
                    af[mt2][1] = f2tf32(As[(rb + gid + 8) * 72 + kc]);
                    af[mt2][2] = f2tf32(As[(rb + gid) * 72 + kc + 4]);
                    af[mt2][3] = f2tf32(As[(rb + gid + 8) * 72 + kc + 4]);
                }
                #pragma unroll
                for (int nt = 0; nt < 8; nt++) {
                    uint32_t b0 = __float_as_uint(Bs[kc * 72 + nt * 8 + gid]);
                    uint32_t b1 = __float_as_uint(Bs[(kc + 4) * 72 + nt * 8 + gid]);
                    mma8(c[0][nt], af[0][0], af[0][1], af[0][2], af[0][3], b0, b1);
                    mma8(c[1][nt], af[1][0], af[1][1], af[1][2], af[1][3], b0, b1);
                }
            }
        }
        cpa_wait<0>();
        __syncthreads();
        // cross-warp-k reduction via smem, then store fp32 partial
        float* red = sm;  // [2][32][64]
        if (wk == 1) {
            #pragma unroll
            for (int mt2 = 0; mt2 < 2; mt2++)
                #pragma unroll
                for (int nt = 0; nt < 8; nt++)
                    #pragma unroll
                    for (int q = 0; q < 4; q++) {
                        int rowl = mt2 * 16 + gid + ((q & 2) ? 8 : 0);
                        int col = nt * 8 + tig * 2 + (q & 1);
                        red[wm * 2048 + rowl * 64 + col] = c[mt2][nt][q];
                    }
        }
        __syncthreads();
        if (wk == 0) {
            #pragma unroll
            for (int mt2 = 0; mt2 < 2; mt2++)
                #pragma unroll
                for (int nt = 0; nt < 8; nt++)
                    #pragma unroll
                    for (int q = 0; q < 4; q++) {
                        int rowl = mt2 * 16 + gid + ((q & 2) ? 8 : 0);
                        int col = nt * 8 + tig * 2 + (q & 1);
                        float v = c[mt2][nt][q] + red[wm * 2048 + rowl * 64 + col];
                        g_part[k8][mt * 64 + wm * 32 + rowl][col] = v;
                    }
        }
        __syncthreads();   // smem (red/stages) safe before next unit
    }
}

// ---------------- K7: reduce 8 split-k partials + leaky relu ----------------
__global__ void sagr_hreduce(float* __restrict__ out) {
    int idx = blockIdx.x * 256 + threadIdx.x;    // 0 .. 524287
    const float* p = &g_part[0][0][0];
    float v = 0.f;
    #pragma unroll
    for (int j = 0; j < 8; j++) v += p[j * 524288 + idx];
    out[idx] = (v > 0.f) ? v : 0.01f * v;
}

// ---------------- diagnostic poison kernel ----------------
__global__ void sagr_poison(float* out, float val) { out[0] = val; }

static void h_threefry(uint32_t k0, uint32_t k1, uint32_t c0, uint32_t c1,
                       uint32_t* o0, uint32_t* o1) {
    uint32_t x0 = c0, x1 = c1;
    uint32_t ks0 = k0, ks1 = k1, ks2 = k0 ^ k1 ^ 0x1BD11BDAu;
    const int R0[4] = {13, 15, 26, 6}, R1[4] = {17, 29, 16, 24};
    auto rl = [](uint32_t x, int r) { return (x << r) | (x >> (32 - r)); };
    x0 += ks0; x1 += ks1;
    for (int i = 0; i < 4; i++) { x0 += x1; x1 = rl(x1, R0[i]); x1 ^= x0; }
    x0 += ks1; x1 += ks2 + 1u;
    for (int i = 0; i < 4; i++) { x0 += x1; x1 = rl(x1, R1[i]); x1 ^= x0; }
    x0 += ks2; x1 += ks0 + 2u;
    for (int i = 0; i < 4; i++) { x0 += x1; x1 = rl(x1, R0[i]); x1 ^= x0; }
    x0 += ks0; x1 += ks1 + 3u;
    for (int i = 0; i < 4; i++) { x0 += x1; x1 = rl(x1, R1[i]); x1 ^= x0; }
    x0 += ks1; x1 += ks2 + 4u;
    for (int i = 0; i < 4; i++) { x0 += x1; x1 = rl(x1, R0[i]); x1 ^= x0; }
    x0 += ks2; x1 += ks0 + 5u;
    *o0 = x0; *o1 = x1;
}

// ---------------- launch ----------------
extern "C" void kernel_launch(void* const* d_in, const int* in_sizes, int n_in,
                              void* d_out, int out_size) {
    (void)out_size;
    int iz = 0, iPref = 1, iPin = 2, iAref = 3, iAin = 4, iR = 5,
        iWiw = 6, iWib = 7, iWgw = 8, iWgb = 9, iWsw = 10, iWsb = 11,
        iWs = 12, iWkw = 13, iWkb = 14;
    if (n_in >= 15 && in_sizes[4] == 8192 * 8192) {
        iAin = 0; iAref = 1; iPin = 2; iPref = 3; iR = 4;
        iWgb = 5; iWgw = 6; iWib = 7; iWiw = 8; iWkb = 9; iWkw = 10;
        iWs = 11; iWsb = 12; iWsw = 13; iz = 14;
    }
    const float* z    = (const float*)d_in[iz];
    const float* Pref = (const float*)d_in[iPref];
    const float* Pin  = (const float*)d_in[iPin];
    const float* Aref = (const float*)d_in[iAref];
    const float* Ain  = (const float*)d_in[iAin];
    const float* R    = (const float*)d_in[iR];
    const float* Wiw  = (const float*)d_in[iWiw];
    const float* Wib  = (const float*)d_in[iWib];
    const float* Wgw  = (const float*)d_in[iWgw];
    const float* Wgb  = (const float*)d_in[iWgb];
    const float* Wsw  = (const float*)d_in[iWsw];
    const float* Wsb  = (const float*)d_in[iWsb];
    const float* Ws   = (const float*)d_in[iWs];
    const float* Wkw  = (const float*)d_in[iWkw];
    const float* Wkb  = (const float*)d_in[iWkb];
    float* out = (float*)d_out;

    cudaFuncSetAttribute(sagr_rowops, cudaFuncAttributeMaxDynamicSharedMemorySize, 17808 * 4);
    cudaFuncSetAttribute(sagr_prop,   cudaFuncAttributeMaxDynamicSharedMemorySize, 19520 * 4);
    cudaFuncSetAttribute(sagr_hgemm6, cudaFuncAttributeMaxDynamicSharedMemorySize, 36864 * 4);

    sagr_stats<<<128, 256>>>(Pin, Ain);
    sagr_finalize<<<1, 256>>>();
    sagr_kg<<<64, 256>>>(Ws, Wkw, Wkb);
    sagr_wf<<<16, 1024>>>(Ws);
    sagr_rowops<<<128, 256, 17808 * 4>>>(z, Pref, Aref, Wiw, Wib, Wgw, Wgb, Wsw, Wsb, out);
    sagr_prop<<<128, 128, 19520 * 4>>>(z);
    sagr_hgemm6<<<148, 128, 36864 * 4>>>(R);
    sagr_hreduce<<<2048, 256>>>(out);

    // KAT self-test: nan -> core broken; 1e9 -> one KAT failed; else OK
    {
        uint32_t a0, a1, b0, b1;
        h_threefry(0u, 0u, 0u, 0u, &a0, &a1);
        h_threefry(0xFFFFFFFFu, 0xFFFFFFFFu, 0xFFFFFFFFu, 0xFFFFFFFFu, &b0, &b1);
        bool t1 = (a0 == 0x6b200159u && a1 == 0x99ba4efeu);
        bool t2 = (b0 == 0x1cb996fcu && b1 == 0xbb002be7u);
        if (!t1 && !t2)    sagr_poison<<<1, 1>>>(out, nanf(""));
        else if (t1 != t2) sagr_poison<<<1, 1>>>(out, 1e9f);
    }
}

// round 17
// speedup vs baseline: 1.1049x; 1.1049x over previous
#include <cuda_runtime.h>
#include <cstdint>
#include <math.h>

// ---------------- problem constants ----------------
#define NROWS 8192
#define DKK   64
#define GMODES 16

// ---------------- static device scratch (no runtime alloc) ----------------
__device__ __align__(16) float g_colpart[2][64][64];
__device__ float g_sqpart[2][64];
__device__ float g_stats[2][65];
__device__ __align__(16) float g_kg[GMODES][64];
__device__ __align__(16) float g_Wf[GMODES * 64][64];   // Wf[g*64+j][i] = tf32(W_s[g][i][j])
__device__ __align__(16) float g_alpha[NROWS][GMODES];
__device__ __align__(16) float g_prop[NROWS][64];       // tf32-rounded propagated[n][i]

// ---------------- helpers ----------------
#define DI static __device__ __forceinline__

DI uint32_t f2tf32(float x) {
    uint32_t r;
    asm("cvt.rna.tf32.f32 %0, %1;" : "=r"(r) : "f"(x));
    return r;
}
DI float round_tf32(float x) { return __uint_as_float(f2tf32(x)); }

DI void mma8(float c[4], uint32_t a0, uint32_t a1, uint32_t a2, uint32_t a3,
             uint32_t b0, uint32_t b1) {
    asm volatile(
        "mma.sync.aligned.m16n8k8.row.col.f32.tf32.tf32.f32 "
        "{%0,%1,%2,%3},{%4,%5,%6,%7},{%8,%9},{%0,%1,%2,%3};\n"
        : "+f"(c[0]), "+f"(c[1]), "+f"(c[2]), "+f"(c[3])
        : "r"(a0), "r"(a1), "r"(a2), "r"(a3), "r"(b0), "r"(b1));
}

DI void cpa16(void* smem, const void* g) {
    uint32_t s = (uint32_t)__cvta_generic_to_shared(smem);
    asm volatile("cp.async.cg.shared.global [%0], [%1], 16;\n" :: "r"(s), "l"(g));
}
DI void cpa_commit() { asm volatile("cp.async.commit_group;\n"); }
template <int NPEND> DI void cpa_wait() { asm volatile("cp.async.wait_group %0;\n" :: "n"(NPEND)); }

DI uint32_t rotl32(uint32_t x, int r) { return (x << r) | (x >> (32 - r)); }

// JAX threefry2x32-20, key (0,42), partitionable: counter (0, m), out = bits1 ^ bits2
DI float gumbel_for(int m) {
    uint32_t x0 = 0u, x1 = (uint32_t)m;
    const uint32_t k0 = 0u, k1 = 42u, k2 = 0u ^ 42u ^ 0x1BD11BDAu;
    const int R0[4] = {13, 15, 26, 6}, R1[4] = {17, 29, 16, 24};
    x0 += k0; x1 += k1;
    #pragma unroll
    for (int i = 0; i < 4; i++) { x0 += x1; x1 = rotl32(x1, R0[i]); x1 ^= x0; }
    x0 += k1; x1 += k2 + 1u;
    #pragma unroll
    for (int i = 0; i < 4; i++) { x0 += x1; x1 = rotl32(x1, R1[i]); x1 ^= x0; }
    x0 += k2; x1 += k0 + 2u;
    #pragma unroll
    for (int i = 0; i < 4; i++) { x0 += x1; x1 = rotl32(x1, R0[i]); x1 ^= x0; }
    x0 += k0; x1 += k1 + 3u;
    #pragma unroll
    for (int i = 0; i < 4; i++) { x0 += x1; x1 = rotl32(x1, R1[i]); x1 ^= x0; }
    x0 += k1; x1 += k2 + 4u;
    #pragma unroll
    for (int i = 0; i < 4; i++) { x0 += x1; x1 = rotl32(x1, R0[i]); x1 ^= x0; }
    x0 += k2; x1 += k0 + 5u;
    uint32_t bits = x0 ^ x1;
    float u = __uint_as_float((bits >> 9) | 0x3f800000u) - 1.0f;
    u = fmaxf(u, 0.0f);
    return -logf(-logf(u + 1e-10f) + 1e-10f);
}

// ---------------- K0: partial stats for P_in / A_in ----------------
__global__ void sagr_stats(const float* __restrict__ Pin, const float* __restrict__ Ain) {
    __shared__ float scs[256], sss[256];
    int b = blockIdx.x, t = threadIdx.x;
    int which = b >> 6, bb = b & 63;
    const float* X = which ? Ain : Pin;
    int c = t & 63, r0 = t >> 6;
    const float* base = X + (size_t)bb * 128 * 64;
    float cs = 0.f, ss = 0.f;
    for (int r = r0; r < 128; r += 4) { float v = base[r * 64 + c]; cs += v; ss += v * v; }
    scs[t] = cs; sss[t] = ss;
    __syncthreads();
    if (t < 64) g_colpart[which][bb][t] = scs[t] + scs[t + 64] + scs[t + 128] + scs[t + 192];
    __syncthreads();
    if (t < 128) sss[t] += sss[t + 128];
    __syncthreads();
    if (t < 64) sss[t] += sss[t + 64];
    __syncthreads();
    if (t < 32) {
        float v = sss[t] + sss[t + 32];
        for (int o = 16; o > 0; o >>= 1) v += __shfl_down_sync(0xffffffffu, v, o);
        if (t == 0) g_sqpart[which][bb] = v;
    }
}

// ---------------- K1: finalize stats ----------------
__global__ void sagr_finalize() {
    int t = threadIdx.x;
    if (t < 128) {
        int which = t >> 6, c = t & 63;
        float s = 0.f;
        for (int bb = 0; bb < 64; bb++) s += g_colpart[which][bb][c];
        g_stats[which][c] = s / 8192.0f;
    } else if (t == 128 || t == 129) {
        int which = t - 128;
        float s = 0.f;
        for (int bb = 0; bb < 64; bb++) s += g_sqpart[which][bb];
        g_stats[which][64] = s / 524288.0f;
    }
}

// ---------------- K2: k_g[g][i] = Ws_flat[g] . Wkw[i] + Wkb[i] ----------------
__global__ void sagr_kg(const float* __restrict__ Ws, const float* __restrict__ Wkw,
                        const float* __restrict__ Wkb) {
    __shared__ float wk_s[4096];
    __shared__ float red[8];
    int i = blockIdx.x, t = threadIdx.x;
    for (int f = t; f < 4096; f += 256) wk_s[f] = Wkw[i * 4096 + f];
    __syncthreads();
    float bias = Wkb[i];
    for (int g = 0; g < GMODES; g++) {
        const float* w = Ws + g * 4096;
        float p = 0.f;
        for (int f = t; f < 4096; f += 256) p += w[f] * wk_s[f];
        for (int o = 16; o > 0; o >>= 1) p += __shfl_down_sync(0xffffffffu, p, o);
        if ((t & 31) == 0) red[t >> 5] = p;
        __syncthreads();
        if (t == 0) {
            float s = 0.f;
            for (int ww = 0; ww < 8; ww++) s += red[ww];
            g_kg[g][i] = s + bias;
        }
        __syncthreads();
    }
}

// ---------------- K3: Wf transpose via smem (1024 threads, coalesced both sides) ----------------
__global__ __launch_bounds__(1024) void sagr_wf(const float* __restrict__ Ws) {
    __shared__ float s[64 * 65];
    int g = blockIdx.x, t = threadIdx.x;
    for (int idx = t; idx < 4096; idx += 1024) {
        int i = idx >> 6, j = idx & 63;
        s[j * 65 + i] = Ws[g * 4096 + idx];
    }
    __syncthreads();
    for (int idx = t; idx < 4096; idx += 1024) {
        int row = idx >> 6, col = idx & 63;
        g_Wf[g * 64 + row][col] = round_tf32(s[row * 65 + col]);
    }
}

// ---------------- K4: fused per-row ops ----------------
__global__ __launch_bounds__(256) void sagr_rowops(
    const float* __restrict__ z, const float* __restrict__ Pref, const float* __restrict__ Aref,
    const float* __restrict__ Wiw, const float* __restrict__ Wib,
    const float* __restrict__ Wgw, const float* __restrict__ Wgb,
    const float* __restrict__ Wsw, const float* __restrict__ Wsb,
    float* __restrict__ out) {
    extern __shared__ float sm[];
    float* z_s  = sm;
    float* wi_s = sm + 4160;
    float* wg_s = sm + 8320;
    float* q_s  = sm + 12480;
    float* kg_s = sm + 16640;
    float* dp_s = sm + 17680;
    float* da_s = sm + 17744;
    int t = threadIdx.x, blk = blockIdx.x, row0 = blk * 64;

    for (int idx = t; idx < 4096; idx += 256) {
        int r = idx >> 6, c = idx & 63;
        z_s[r * 65 + c]  = z[(row0 + r) * 64 + c];
        wi_s[r * 65 + c] = Wiw[idx];
        wg_s[r * 65 + c] = Wgw[idx];
    }
    for (int idx = t; idx < 1024; idx += 256) {
        int g = idx >> 6, c = idx & 63;
        kg_s[g * 65 + c] = g_kg[g][c];
    }
    {
        int r = t >> 2, u = t & 3, n = row0 + r;
        float dotP = 0.f, sqP = 0.f, dotA = 0.f, sqA = 0.f;
        for (int kk = 0; kk < 16; kk++) {
            int k = u * 16 + kk;
            float pv = Pref[n * 64 + k]; dotP += pv * g_stats[0][k]; sqP += pv * pv;
            float av = Aref[n * 64 + k]; dotA += av * g_stats[1][k]; sqA += av * av;
        }
        dotP += __shfl_xor_sync(0xffffffffu, dotP, 1); dotP += __shfl_xor_sync(0xffffffffu, dotP, 2);
        sqP  += __shfl_xor_sync(0xffffffffu, sqP, 1);  sqP  += __shfl_xor_sync(0xffffffffu, sqP, 2);
        dotA += __shfl_xor_sync(0xffffffffu, dotA, 1); dotA += __shfl_xor_sync(0xffffffffu, dotA, 2);
        sqA  += __shfl_xor_sync(0xffffffffu, sqA, 1);  sqA  += __shfl_xor_sync(0xffffffffu, sqA, 2);
        if (u == 0) {
            dp_s[r] = g_stats[0][64] - 2.0f * dotP / 64.0f + sqP / 64.0f;
            da_s[r] = g_stats[1][64] - 2.0f * dotA / 64.0f + sqA / 64.0f;
        }
    }
    __syncthreads();
    {
        int grp = t >> 4, il = t & 15;
        int r0 = grp * 4, i0 = il * 4;
        float aI[4][4] = {}, aG[4][4] = {};
        for (int j = 0; j < 64; j++) {
            float zz[4], wi4[4], wg4[4];
            #pragma unroll
            for (int rr = 0; rr < 4; rr++) zz[rr] = z_s[(r0 + rr) * 65 + j];
            #pragma unroll
            for (int ii = 0; ii < 4; ii++) { wi4[ii] = wi_s[(i0 + ii) * 65 + j]; wg4[ii] = wg_s[(i0 + ii) * 65 + j]; }
            #pragma unroll
            for (int rr = 0; rr < 4; rr++)
                #pragma unroll
                for (int ii = 0; ii < 4; ii++) {
                    aI[rr][ii] += zz[rr] * wi4[ii];
                    aG[rr][ii] += zz[rr] * wg4[ii];
                }
        }
        #pragma unroll
        for (int ii = 0; ii < 4; ii++) {
            int i = i0 + ii;
            float bi = Wib[i], bg = Wgb[i], bs = Wsb[i];
            float w0 = Wsw[i * 2 + 0], w1 = Wsw[i * 2 + 1];
            #pragma unroll
            for (int rr = 0; rr < 4; rr++) {
                int r = r0 + rr;
                float gate = 1.0f / (1.0f + expf(-(aG[rr][ii] + bg)));
                float sys = da_s[r] * w0 + dp_s[r] * w1 + bs;
                q_s[r * 65 + i] = aI[rr][ii] + bi + gate * sys;
            }
        }
    }
    __syncthreads();
    {
        int r = t >> 2, u = t & 3, n = row0 + r;
        float acc[4] = {0.f, 0.f, 0.f, 0.f};
        for (int i = 0; i < 64; i++) {
            float qv = q_s[r * 65 + i];
            #pragma unroll
            for (int gg = 0; gg < 4; gg++) acc[gg] += qv * kg_s[(u * 4 + gg) * 65 + i];
        }
        float e[4], mx = -1e30f;
        #pragma unroll
        for (int gg = 0; gg < 4; gg++) {
            int g = u * 4 + gg;
            float s = acc[gg] * 0.125f;
            out[NROWS * 64 + n * 16 + g] = s;
            e[gg] = s + gumbel_for(n * 16 + g);
            mx = fmaxf(mx, e[gg]);
        }
        mx = fmaxf(mx, __shfl_xor_sync(0xffffffffu, mx, 1));
        mx = fmaxf(mx, __shfl_xor_sync(0xffffffffu, mx, 2));
        float sum = 0.f;
        #pragma unroll
        for (int gg = 0; gg < 4; gg++) { e[gg] = expf(e[gg] - mx); sum += e[gg]; }
        sum += __shfl_xor_sync(0xffffffffu, sum, 1);
        sum += __shfl_xor_sync(0xffffffffu, sum, 2);
        float inv = 1.0f / sum;
        #pragma unroll
        for (int gg = 0; gg < 4; gg++) g_alpha[n][u * 4 + gg] = e[gg] * inv;
    }
}

// ---------------- K5: propagated = (alpha (x) z) @ Wf, tf32 mma (R6-exact) ----------------
__global__ __launch_bounds__(128) void sagr_prop(const float* __restrict__ z) {
    extern __shared__ float sm[];
    float* z_s  = sm;               // 64 x 72
    float* al_s = sm + 4608;        // 64 x 17
    float* wf_s = sm + 4608 + 1088; // 2 buffers of 64 x 72
    int t = threadIdx.x, w = t >> 5, lane = t & 31;
    int gid = lane >> 2, tig = lane & 3;
    int row0 = blockIdx.x * 64;

    for (int idx = t; idx < 4096; idx += 128) {
        int r = idx >> 6, c = idx & 63;
        z_s[r * 72 + c] = z[(row0 + r) * 64 + c];
    }
    for (int idx = t; idx < 1024; idx += 128) {
        int r = idx >> 4, g = idx & 15;
        al_s[r * 17 + g] = g_alpha[row0 + r][g];
    }
    {
        #pragma unroll
        for (int it = 0; it < 8; it++) {
            int chunk = it * 128 + t, row = chunk >> 4, cc = chunk & 15;
            cpa16(wf_s + row * 72 + cc * 4, &g_Wf[row][cc * 4]);
        }
        cpa_commit();
    }
    float c[8][4] = {};
    int r0g = w * 16 + gid;
    for (int g = 0; g < GMODES; g++) {
        cpa_wait<0>();
        __syncthreads();
        if (g < 15) {
            int buf2 = (g + 1) & 1;
            #pragma unroll
            for (int it = 0; it < 8; it++) {
                int chunk = it * 128 + t, row = chunk >> 4, cc = chunk & 15;
                cpa16(wf_s + buf2 * 4608 + row * 72 + cc * 4, &g_Wf[(g + 1) * 64 + row][cc * 4]);
            }
            cpa_commit();
        }
        float* wb = wf_s + (g & 1) * 4608;
        float a_lo = al_s[r0g * 17 + g];
        float a_hi = al_s[(r0g + 8) * 17 + g];
        #pragma unroll
        for (int ks = 0; ks < 8; ks++) {
            int kc = ks * 8 + tig;
            uint32_t a0 = f2tf32(a_lo * z_s[r0g * 72 + kc]);
            uint32_t a1 = f2tf32(a_hi * z_s[(r0g + 8) * 72 + kc]);
            uint32_t a2 = f2tf32(a_lo * z_s[r0g * 72 + kc + 4]);
            uint32_t a3 = f2tf32(a_hi * z_s[(r0g + 8) * 72 + kc + 4]);
            #pragma unroll
            for (int nt = 0; nt < 8; nt++) {
                uint32_t b0 = __float_as_uint(wb[kc * 72 + nt * 8 + gid]);
                uint32_t b1 = __float_as_uint(wb[(kc + 4) * 72 + nt * 8 + gid]);
                mma8(c[nt], a0, a1, a2, a3, b0, b1);
            }
        }
    }
    #pragma unroll
    for (int nt = 0; nt < 8; nt++)
        #pragma unroll
        for (int q = 0; q < 4; q++) {
            int row = r0g + ((q & 2) ? 8 : 0);
            int col = nt * 8 + tig * 2 + (q & 1);
            g_prop[row0 + row][col] = round_tf32(c[nt][q]);
        }
}

// ---------------- K6: h = leaky_relu(R @ prop), tf32 mma, 4-stage cp.async (R6-exact) ----------------
__global__ __launch_bounds__(128) void sagr_hgemm(const float* __restrict__ R, float* __restrict__ out) {
    extern __shared__ float sm[];
    int t = threadIdx.x, w = t >> 5, lane = t & 31;
    int gid = lane >> 2, tig = lane & 3;
    int wm = w >> 1, wk = w & 1;
    int bm = blockIdx.x;
    const float* Rbase = R + (size_t)(bm * 64) * 8192;
    float c[2][8][4] = {};

    auto issue = [&](int kt, int s) {
        float* As = sm + s * 9216;
        float* Bs = As + 4608;
        const float* ra = Rbase + kt * 64;
        #pragma unroll
        for (int it = 0; it < 8; it++) {
            int chunk = it * 128 + t, row = chunk >> 4, cc = chunk & 15;
            cpa16(As + row * 72 + cc * 4, ra + (size_t)row * 8192 + cc * 4);
        }
        const float* pb = &g_prop[kt * 64][0];
        #pragma unroll
        for (int it = 0; it < 8; it++) {
            int chunk = it * 128 + t, row = chunk >> 4, cc = chunk & 15;
            cpa16(Bs + row * 72 + cc * 4, pb + row * 64 + cc * 4);
        }
    };

    issue(0, 0); cpa_commit();
    issue(1, 1); cpa_commit();
    issue(2, 2); cpa_commit();

    for (int kt = 0; kt < 128; kt++) {
        cpa_wait<2>();
        __syncthreads();
        if (kt + 3 < 128) issue(kt + 3, (kt + 3) & 3);
        cpa_commit();
        float* As = sm + (kt & 3) * 9216;
        float* Bs = As + 4608;
        #pragma unroll
        for (int ks = 0; ks < 4; ks++) {
            int kc = wk * 32 + ks * 8 + tig;
            uint32_t af[2][4];
            #pragma unroll
            for (int mt = 0; mt < 2; mt++) {
                int rb = wm * 32 + mt * 16;
                af[mt][0] = f2tf32(As[(rb + gid) * 72 + kc]);
                af[mt][1] = f2tf32(As[(rb + gid + 8) * 72 + kc]);
                af[mt][2] = f2tf32(As[(rb + gid) * 72 + kc + 4]);
                af[mt][3] = f2tf32(As[(rb + gid + 8) * 72 + kc + 4]);
            }
            #pragma unroll
            for (int nt = 0; nt < 8; nt++) {
                uint32_t b0 = __float_as_uint(Bs[kc * 72 + nt * 8 + gid]);
                uint32_t b1 = __float_as_uint(Bs[(kc + 4) * 72 + nt * 8 + gid]);
                mma8(c[0][nt], af[0][0], af[0][1], af[0][2], af[0][3], b0, b1);
                mma8(c[1][nt], af[1][0], af[1][1], af[1][2], af[1][3], b0, b1);
            }
        }
    }
    cpa_wait<0>();
    __syncthreads();
    float* red = sm;  // [2][32][64]
    if (wk == 1) {
        #pragma unroll
        for (int mt = 0; mt < 2; mt++)
            #pragma unroll
            for (int nt = 0; nt < 8; nt++)
                #pragma unroll
                for (int q = 0; q < 4; q++) {
                    int rowl = mt * 16 + gid + ((q & 2) ? 8 : 0);
                    int col = nt * 8 + tig * 2 + (q & 1);
                    red[wm * 2048 + rowl * 64 + col] = c[mt][nt][q];
                }
    }
    __syncthreads();
    if (wk == 0) {
        #pragma unroll
        for (int mt = 0; mt < 2; mt++)
            #pragma unroll
            for (int nt = 0; nt < 8; nt++)
                #pragma unroll
                for (int q = 0; q < 4; q++) {
                    int rowl = mt * 16 + gid + ((q & 2) ? 8 : 0);
                    int col = nt * 8 + tig * 2 + (q & 1);
                    float v = c[mt][nt][q] + red[wm * 2048 + rowl * 64 + col];
                    v = (v > 0.f) ? v : 0.01f * v;
                    out[(bm * 64 + wm * 32 + rowl) * 64 + col] = v;
                }
    }
}

// ---------------- diagnostic poison kernel ----------------
__global__ void sagr_poison(float* out, float val) { out[0] = val; }

static void h_threefry(uint32_t k0, uint32_t k1, uint32_t c0, uint32_t c1,
                       uint32_t* o0, uint32_t* o1) {
    uint32_t x0 = c0, x1 = c1;
    uint32_t ks0 = k0, ks1 = k1, ks2 = k0 ^ k1 ^ 0x1BD11BDAu;
    const int R0[4] = {13, 15, 26, 6}, R1[4] = {17, 29, 16, 24};
    auto rl = [](uint32_t x, int r) { return (x << r) | (x >> (32 - r)); };
    x0 += ks0; x1 += ks1;
    for (int i = 0; i < 4; i++) { x0 += x1; x1 = rl(x1, R0[i]); x1 ^= x0; }
    x0 += ks1; x1 += ks2 + 1u;
    for (int i = 0; i < 4; i++) { x0 += x1; x1 = rl(x1, R1[i]); x1 ^= x0; }
    x0 += ks2; x1 += ks0 + 2u;
    for (int i = 0; i < 4; i++) { x0 += x1; x1 = rl(x1, R0[i]); x1 ^= x0; }
    x0 += ks0; x1 += ks1 + 3u;
    for (int i = 0; i < 4; i++) { x0 += x1; x1 = rl(x1, R1[i]); x1 ^= x0; }
    x0 += ks1; x1 += ks2 + 4u;
    for (int i = 0; i < 4; i++) { x0 += x1; x1 = rl(x1, R0[i]); x1 ^= x0; }
    x0 += ks2; x1 += ks0 + 5u;
    *o0 = x0; *o1 = x1;
}

// ---------------- launch ----------------
extern "C" void kernel_launch(void* const* d_in, const int* in_sizes, int n_in,
                              void* d_out, int out_size) {
    (void)out_size;
    int iz = 0, iPref = 1, iPin = 2, iAref = 3, iAin = 4, iR = 5,
        iWiw = 6, iWib = 7, iWgw = 8, iWgb = 9, iWsw = 10, iWsb = 11,
        iWs = 12, iWkw = 13, iWkb = 14;
    if (n_in >= 15 && in_sizes[4] == 8192 * 8192) {
        iAin = 0; iAref = 1; iPin = 2; iPref = 3; iR = 4;
        iWgb = 5; iWgw = 6; iWib = 7; iWiw = 8; iWkb = 9; iWkw = 10;
        iWs = 11; iWsb = 12; iWsw = 13; iz = 14;
    }
    const float* z    = (const float*)d_in[iz];
    const float* Pref = (const float*)d_in[iPref];
    const float* Pin  = (const float*)d_in[iPin];
    const float* Aref = (const float*)d_in[iAref];
    const float* Ain  = (const float*)d_in[iAin];
    const float* R    = (const float*)d_in[iR];
    const float* Wiw  = (const float*)d_in[iWiw];
    const float* Wib  = (const float*)d_in[iWib];
    const float* Wgw  = (const float*)d_in[iWgw];
    const float* Wgb  = (const float*)d_in[iWgb];
    const float* Wsw  = (const float*)d_in[iWsw];
    const float* Wsb  = (const float*)d_in[iWsb];
    const float* Ws   = (const float*)d_in[iWs];
    const float* Wkw  = (const float*)d_in[iWkw];
    const float* Wkb  = (const float*)d_in[iWkb];
    float* out = (float*)d_out;

    cudaFuncSetAttribute(sagr_rowops, cudaFuncAttributeMaxDynamicSharedMemorySize, 17808 * 4);
    cudaFuncSetAttribute(sagr_prop,   cudaFuncAttributeMaxDynamicSharedMemorySize, 14912 * 4);
    cudaFuncSetAttribute(sagr_hgemm,  cudaFuncAttributeMaxDynamicSharedMemorySize, 36864 * 4);

    sagr_stats<<<128, 256>>>(Pin, Ain);
    sagr_finalize<<<1, 256>>>();
    sagr_kg<<<64, 256>>>(Ws, Wkw, Wkb);
    sagr_wf<<<16, 1024>>>(Ws);
    sagr_rowops<<<128, 256, 17808 * 4>>>(z, Pref, Aref, Wiw, Wib, Wgw, Wgb, Wsw, Wsb, out);
    sagr_prop<<<128, 128, 14912 * 4>>>(z);
    sagr_hgemm<<<128, 128, 36864 * 4>>>(R, out);

    // KAT self-test: nan -> core broken; 1e9 -> one KAT failed; else OK
    {
        uint32_t a0, a1, b0, b1;
        h_threefry(0u, 0u, 0u, 0u, &a0, &a1);
        h_threefry(0xFFFFFFFFu, 0xFFFFFFFFu, 0xFFFFFFFFu, 0xFFFFFFFFu, &b0, &b1);
        bool t1 = (a0 == 0x6b200159u && a1 == 0x99ba4efeu);
        bool t2 = (b0 == 0x1cb996fcu && b1 == 0xbb002be7u);
        if (!t1 && !t2)    sagr_poison<<<1, 1>>>(out, nanf(""));
        else if (t1 != t2) sagr_poison<<<1, 1>>>(out, 1e9f);
    }
}